// round 17
// baseline (speedup 1.0000x reference)
#include <cuda_runtime.h>
#include <cuda_bf16.h>
#include <cstdint>
#include <cmath>

// Problem constants
#define S_LEN   1024
#define DMODEL  1024
#define H_NUM   16
#define DH      64
#define BATCH   2
#define NCH     32     // chunks along S
#define CHS     32     // chunk length (S_LEN / NCH)
#define NBLK    (BATCH * H_NUM * NCH)   // 1024 scan blocks
#define NBHP    (BATCH * H_NUM * 5)     // 160 prefix rows

// Scratch (static device globals; no allocation allowed)
__device__ float g_qkv[(size_t)BATCH * S_LEN * 3 * DMODEL];   // 25.2 MB
__device__ float g_ckv[NBHP * NCH * DH];                      // kv chunk sums -> exclusive prefix
__device__ float g_crk[NBHP * NCH];                           // rk chunk sums -> exclusive prefix
__device__ volatile unsigned g_bar1;
__device__ volatile unsigned g_bar2;

// bf16 hi/lo split operands
__device__ __nv_bfloat16 g_xh[(size_t)BATCH * S_LEN * DMODEL];
__device__ __nv_bfloat16 g_xl[(size_t)BATCH * S_LEN * DMODEL];
__device__ __nv_bfloat16 g_wih[(size_t)3 * DMODEL * DMODEL];
__device__ __nv_bfloat16 g_wil[(size_t)3 * DMODEL * DMODEL];
__device__ __nv_bfloat16 g_woh[(size_t)DMODEL * DMODEL];
__device__ __nv_bfloat16 g_wol[(size_t)DMODEL * DMODEL];
__device__ __nv_bfloat16 g_ath[(size_t)BATCH * S_LEN * DMODEL];
__device__ __nv_bfloat16 g_atl[(size_t)BATCH * S_LEN * DMODEL];

struct Betas { float b[5]; };

__device__ __forceinline__ float clampx(float x) {
    return fminf(fmaxf(x, -1.0f + 1e-6f), 1.0f - 1e-6f);
}

__device__ __forceinline__ void cheb5(float x, float t[5]) {
    float x2 = x + x;
    float t1 = x;
    float t2 = x2 * t1 - 1.0f;
    float t3 = x2 * t2 - t1;
    float t4 = x2 * t3 - t2;
    float t5 = x2 * t4 - t3;
    t[0] = t1; t[1] = t2; t[2] = t3; t[3] = t4; t[4] = t5;
}

__device__ __forceinline__ unsigned pack2(__nv_bfloat16 a, __nv_bfloat16 b) {
    __nv_bfloat162 t(a, b);
    return *reinterpret_cast<unsigned*>(&t);
}

__device__ __forceinline__ void ldsm4(unsigned& r0, unsigned& r1, unsigned& r2, unsigned& r3,
                                      unsigned addr) {
    asm volatile("ldmatrix.sync.aligned.m8n8.x4.shared.b16 {%0,%1,%2,%3}, [%4];"
                 : "=r"(r0), "=r"(r1), "=r"(r2), "=r"(r3) : "r"(addr));
}

__device__ __forceinline__ void mma_bf16(float c[4],
                                         unsigned a0, unsigned a1, unsigned a2, unsigned a3,
                                         unsigned b0, unsigned b1) {
    asm volatile(
        "mma.sync.aligned.m16n8k16.row.col.f32.bf16.bf16.f32 "
        "{%0,%1,%2,%3}, {%4,%5,%6,%7}, {%8,%9}, {%0,%1,%2,%3};"
        : "+f"(c[0]), "+f"(c[1]), "+f"(c[2]), "+f"(c[3])
        : "r"(a0), "r"(a1), "r"(a2), "r"(a3), "r"(b0), "r"(b1));
}

#define CP16(dst, src) \
    asm volatile("cp.async.cg.shared.global [%0], [%1], 16;" :: "r"(dst), "l"(src))
#define CP_COMMIT() asm volatile("cp.async.commit_group;")
#define CP_WAIT1()  asm volatile("cp.async.wait_group 1;")
#define CP_WAIT0()  asm volatile("cp.async.wait_group 0;")

// swizzled byte offset inside a (rows x 32) bf16 tile (64B rows).
__device__ __forceinline__ unsigned swz(int m, int cbyte) {
    return (unsigned)((m << 6) + (cbyte ^ (((m >> 1) & 3) << 4)));
}

// ---------------------------------------------------------------------------
// split3: f32 -> bf16 hi + bf16 lo residual; also resets the scan barriers.
// ---------------------------------------------------------------------------
__global__ __launch_bounds__(256) void split3(
    const float* __restrict__ a, __nv_bfloat16* __restrict__ ah, __nv_bfloat16* __restrict__ al, int na,
    const float* __restrict__ b, __nv_bfloat16* __restrict__ bh, __nv_bfloat16* __restrict__ bl, int nb,
    const float* __restrict__ c, __nv_bfloat16* __restrict__ ch, __nv_bfloat16* __restrict__ cl, int nc)
{
    if (blockIdx.x == 0 && threadIdx.x == 0) { g_bar1 = 0u; g_bar2 = 0u; }

    int i = (blockIdx.x * blockDim.x + threadIdx.x) * 4;
    const float* src; __nv_bfloat16 *hi, *lo; int off;
    if (i < na)           { src = a; hi = ah; lo = al; off = i; }
    else if (i < na + nb) { src = b; hi = bh; lo = bl; off = i - na; }
    else if (i < na + nb + nc) { src = c; hi = ch; lo = cl; off = i - na - nb; }
    else return;

    float4 v = *(const float4*)(src + off);
    __nv_bfloat16 h0 = __float2bfloat16(v.x), h1 = __float2bfloat16(v.y);
    __nv_bfloat16 h2 = __float2bfloat16(v.z), h3 = __float2bfloat16(v.w);
    __nv_bfloat16 l0 = __float2bfloat16(v.x - __bfloat162float(h0));
    __nv_bfloat16 l1 = __float2bfloat16(v.y - __bfloat162float(h1));
    __nv_bfloat16 l2 = __float2bfloat16(v.z - __bfloat162float(h2));
    __nv_bfloat16 l3 = __float2bfloat16(v.w - __bfloat162float(h3));
    *(uint2*)(hi + off) = make_uint2(pack2(h0, h1), pack2(h2, h3));
    *(uint2*)(lo + off) = make_uint2(pack2(l0, l1), pack2(l2, l3));
}

// ---------------------------------------------------------------------------
// bf16x3 GEMM, pre-split operands, 3-stage cp.async pipeline (1 sync/tile):
//   C[M,N] = (Ah+Al)[M,K] @ (Bh+Bl)[N,K]^T  (drop Al*Bl)
// BM=128, BN template (128 or 64), BK=32, 256 threads (8 warps).
//   BN=128: warps 2m x 4n, warp tile 64x32, MF=4.
//   BN=64 : warps 4m x 2n, warp tile 32x32, MF=2 (small-N GEMM: more CTAs).
// 3 stages x (16KB A + BN*128B B); both variants fit 2 CTAs/SM.
// ---------------------------------------------------------------------------
template <int BN>
__global__ __launch_bounds__(256) void gemm_split(
    const __nv_bfloat16* __restrict__ Ahg, const __nv_bfloat16* __restrict__ Alg,
    const __nv_bfloat16* __restrict__ Bhg, const __nv_bfloat16* __restrict__ Blg,
    float* __restrict__ C, int M, int N, int K)
{
    constexpr int MF    = (BN == 128) ? 4 : 2;      // A fragments per warp
    constexpr int BITER = BN / 64;                  // B copy iterations
    constexpr unsigned BBYTES = BN * 64u;           // one B array (rows x 64B)
    constexpr unsigned OFF_AL = 8192u;
    constexpr unsigned OFF_BH = 16384u;
    constexpr unsigned OFF_BL = 16384u + BBYTES;
    constexpr unsigned STG    = 16384u + 2u * BBYTES;

    extern __shared__ char dsmem[];
    const unsigned smem_u32 = (unsigned)__cvta_generic_to_shared(dsmem);

    const int tid  = threadIdx.x;
    const int wid  = tid >> 5;
    const int lane = tid & 31;
    const int wm = (BN == 128) ? (wid >> 2) * 64 : (wid >> 1) * 32;
    const int wn = (BN == 128) ? (wid & 3) * 32  : (wid & 1) * 32;

    const int bm = blockIdx.y * 128;
    const int bn = blockIdx.x * BN;

    // copy mapping: chunk c = tid + i*256; row = c>>2; 4x16B chunks per 64B row
    int crow[2], ccb[2];
    size_t aoff[2], boff[BITER];
    unsigned dswA[2], dswB[BITER];
#pragma unroll
    for (int i = 0; i < 2; i++) {
        int c = tid + i * 256;
        crow[i] = c >> 2;
        ccb[i]  = (c & 3) * 16;
        aoff[i] = (size_t)(bm + crow[i]) * K * 2 + ccb[i];
        dswA[i] = swz(crow[i], ccb[i]);
    }
#pragma unroll
    for (int i = 0; i < BITER; i++) {
        boff[i] = (size_t)(bn + crow[i]) * K * 2 + ccb[i];
        dswB[i] = dswA[i];
    }
    const char* Ahc = (const char*)Ahg;
    const char* Alc = (const char*)Alg;
    const char* Bhc = (const char*)Bhg;
    const char* Blc = (const char*)Blg;

    auto issue_stage = [&](int stg, int k0) {
        unsigned sb = smem_u32 + (unsigned)stg * STG;
        size_t kb = (size_t)k0 * 2;
#pragma unroll
        for (int i = 0; i < 2; i++) {
            unsigned d = sb + dswA[i];
            CP16(d,          Ahc + aoff[i] + kb);
            CP16(d + OFF_AL, Alc + aoff[i] + kb);
        }
#pragma unroll
        for (int i = 0; i < BITER; i++) {
            unsigned d = sb + dswB[i];
            CP16(d + OFF_BH, Bhc + boff[i] + kb);
            CP16(d + OFF_BL, Blc + boff[i] + kb);
        }
        CP_COMMIT();
    };

    float acc[MF][4][4];
#pragma unroll
    for (int i = 0; i < MF; i++)
#pragma unroll
        for (int j = 0; j < 4; j++)
#pragma unroll
            for (int r = 0; r < 4; r++) acc[i][j][r] = 0.0f;

    const int lt = lane >> 3, lr = lane & 7;
    unsigned a_base[MF], b_base[2];
#pragma unroll
    for (int mf = 0; mf < MF; mf++) {
        int m = wm + mf * 16 + (lt & 1) * 8 + lr;
        a_base[mf] = swz(m, (lt >> 1) * 16);
    }
#pragma unroll
    for (int np = 0; np < 2; np++) {
        int n = wn + np * 16 + (lt >> 1) * 8 + lr;
        b_base[np] = swz(n, (lt & 1) * 16);
    }

    const int nk = K / 32;
    issue_stage(0, 0);
    issue_stage(1, 32);

    int cur = 0, nxt = 2;
    for (int kt = 0; kt < nk; kt++) {
        if (kt + 2 < nk) { CP_WAIT1(); } else { CP_WAIT0(); }
        __syncthreads();
        if (kt + 2 < nk) issue_stage(nxt, (kt + 2) * 32);

        const unsigned st = smem_u32 + (unsigned)cur * STG;
        const unsigned sAh = st, sAl = st + OFF_AL, sBh = st + OFF_BH, sBl = st + OFF_BL;

#pragma unroll
        for (int kk = 0; kk < 2; kk++) {
            const unsigned kb = kk * 32;   // XOR advance (bit 5 within swizzle field)
            unsigned ah[MF][4], al[MF][4];
#pragma unroll
            for (int mf = 0; mf < MF; mf++) {
                ldsm4(ah[mf][0], ah[mf][1], ah[mf][2], ah[mf][3], sAh + (a_base[mf] ^ kb));
                ldsm4(al[mf][0], al[mf][1], al[mf][2], al[mf][3], sAl + (a_base[mf] ^ kb));
            }
            unsigned bhf[4][2], blf[4][2];
#pragma unroll
            for (int np = 0; np < 2; np++) {
                ldsm4(bhf[2 * np][0], bhf[2 * np][1], bhf[2 * np + 1][0], bhf[2 * np + 1][1],
                      sBh + (b_base[np] ^ kb));
                ldsm4(blf[2 * np][0], blf[2 * np][1], blf[2 * np + 1][0], blf[2 * np + 1][1],
                      sBl + (b_base[np] ^ kb));
            }
            // Pass 1: hh
#pragma unroll
            for (int mf = 0; mf < MF; mf++)
#pragma unroll
                for (int nf = 0; nf < 4; nf++)
                    mma_bf16(acc[mf][nf], ah[mf][0], ah[mf][1], ah[mf][2], ah[mf][3],
                             bhf[nf][0], bhf[nf][1]);
            // Pass 2: hl
#pragma unroll
            for (int mf = 0; mf < MF; mf++)
#pragma unroll
                for (int nf = 0; nf < 4; nf++)
                    mma_bf16(acc[mf][nf], ah[mf][0], ah[mf][1], ah[mf][2], ah[mf][3],
                             blf[nf][0], blf[nf][1]);
            // Pass 3: lh
#pragma unroll
            for (int mf = 0; mf < MF; mf++)
#pragma unroll
                for (int nf = 0; nf < 4; nf++)
                    mma_bf16(acc[mf][nf], al[mf][0], al[mf][1], al[mf][2], al[mf][3],
                             bhf[nf][0], bhf[nf][1]);
        }
        cur = (cur + 1 == 3) ? 0 : cur + 1;
        nxt = (nxt + 1 == 3) ? 0 : nxt + 1;
    }

    const int g = lane >> 2, th = lane & 3;
#pragma unroll
    for (int mf = 0; mf < MF; mf++) {
#pragma unroll
        for (int nf = 0; nf < 4; nf++) {
            int row = bm + wm + mf * 16 + g;
            int col = bn + wn + nf * 8 + 2 * th;
            *(float2*)(C + (size_t)row * N + col) =
                make_float2(acc[mf][nf][0], acc[mf][nf][1]);
            *(float2*)(C + (size_t)(row + 8) * N + col) =
                make_float2(acc[mf][nf][2], acc[mf][nf][3]);
        }
    }
}

// ---------------------------------------------------------------------------
// scan_fused: chunk sums + cross-chunk prefix + den + final in ONE persistent
// kernel. 1024 blocks x 64 threads, all co-resident.
// ---------------------------------------------------------------------------
__global__ __launch_bounds__(64) void scan_fused(Betas bt)
{
    const int blk = blockIdx.x;                 // b*512 + h*32 + c
    const int c = blk & 31, h = (blk >> 5) & 15, b = blk >> 9;
    const int bh = b * H_NUM + h;
    const int tid = threadIdx.x;
    const int d = tid;

    __shared__ float sq[CHS][DH];
    __shared__ float sk[CHS][DH];
    __shared__ float sv[CHS][DH];
    __shared__ float part[10][32];
    __shared__ float sden[CHS];

    // ---- stage q/k/v for this chunk (once; reused by all phases) ----
    {
        const float* qb = g_qkv + ((size_t)(b * S_LEN + c * CHS)) * (3 * DMODEL) + h * DH;
        for (int i = tid; i < CHS * 16; i += 64) {
            int s = i >> 4, d4 = (i & 15) * 4;
            const float* row = qb + (size_t)s * (3 * DMODEL) + d4;
            *(float4*)&sq[s][d4] = *(const float4*)row;
            *(float4*)&sk[s][d4] = *(const float4*)(row + DMODEL);
            *(float4*)&sv[s][d4] = *(const float4*)(row + 2 * DMODEL);
        }
    }
    __syncthreads();

    // ---- Phase 1: chunk sums ----
    {
        float kv[5] = {0, 0, 0, 0, 0};
        float rk[5] = {0, 0, 0, 0, 0};
#pragma unroll 4
        for (int s = 0; s < CHS; s++) {
            float t[5];
            cheb5(clampx(sk[s][d] * 0.125f), t);
            float vval = sv[s][d];
#pragma unroll
            for (int p = 0; p < 5; p++) { kv[p] += t[p] * vval; rk[p] += t[p]; }
        }
#pragma unroll
        for (int p = 0; p < 5; p++)
            g_ckv[(((size_t)bh * 5 + p) * NCH + c) * DH + d] = kv[p];

        const int lane = d & 31, w = d >> 5;
#pragma unroll
        for (int p = 0; p < 5; p++) {
            float v = rk[p];
#pragma unroll
            for (int o = 16; o > 0; o >>= 1) v += __shfl_down_sync(0xffffffffu, v, o);
            if (lane == 0) part[p][w] = v;   // reuse part[] as scratch
        }
        __syncthreads();
        if (d == 0) {
#pragma unroll
            for (int p = 0; p < 5; p++)
                g_crk[((size_t)bh * 5 + p) * NCH + c] = part[p][0] + part[p][1];
        }
    }
    __threadfence();
    __syncthreads();
    if (tid == 0) atomicAdd((unsigned*)&g_bar1, 1u);

    // ---- Phase 2: prefix (blocks 0..159, bhp = blk) ----
    if (blk < NBHP) {
        if (tid == 0) { while (g_bar1 < (unsigned)NBLK) __nanosleep(128); }
        __syncthreads();
        __threadfence();

        const size_t base = (size_t)blk * NCH * DH + d;
        float vals[NCH];
#pragma unroll
        for (int i = 0; i < NCH; i++) vals[i] = g_ckv[base + (size_t)i * DH];
        float run = 0.0f;
#pragma unroll
        for (int i = 0; i < NCH; i++) {
            g_ckv[base + (size_t)i * DH] = run;
            run += vals[i];
        }
        if (tid < 32) {
            const size_t rb = (size_t)blk * NCH;
            float v = g_crk[rb + tid];
            float inc = v;
#pragma unroll
            for (int o = 1; o < 32; o <<= 1) {
                float t = __shfl_up_sync(0xffffffffu, inc, o);
                if (tid >= o) inc += t;
            }
            g_crk[rb + tid] = inc - v;
        }
        __threadfence();
        __syncthreads();
        if (tid == 0) atomicAdd((unsigned*)&g_bar2, 1u);
    }

    // ---- wait for all prefixes ----
    if (tid == 0) { while (g_bar2 < (unsigned)NBHP) __nanosleep(128); }
    __syncthreads();
    __threadfence();

    // ---- Phase 3a: den (from staged smem) ----
    {
        const int sl = tid & 31;
        const int w  = tid >> 5;
        const int db = w * 32;

        float Aq[5] = {0, 0, 0, 0, 0};
        float Rk[5] = {0, 0, 0, 0, 0};
#pragma unroll
        for (int j = 0; j < 32; j++) {
            float tq[5], tk[5];
            cheb5(clampx(sq[sl][db + j] * 0.125f), tq);
            cheb5(clampx(sk[sl][db + j] * 0.125f), tk);
#pragma unroll
            for (int p = 0; p < 5; p++) { Aq[p] += tq[p]; Rk[p] += tk[p]; }
        }

        __syncthreads();   // part[] scratch reuse safety
        if (w == 1) {
#pragma unroll
            for (int p = 0; p < 5; p++) { part[p][sl] = Aq[p]; part[5 + p][sl] = Rk[p]; }
        }
        __syncthreads();
        if (w == 0) {
#pragma unroll
            for (int p = 0; p < 5; p++) { Aq[p] += part[p][sl]; Rk[p] += part[5 + p][sl]; }

            float dsum = 0.0f;
#pragma unroll
            for (int p = 0; p < 5; p++) {
                float v = Rk[p];
#pragma unroll
                for (int o = 1; o < 32; o <<= 1) {
                    float t = __shfl_up_sync(0xffffffffu, v, o);
                    if (sl >= o) v += t;
                }
                float C = v + g_crk[((size_t)bh * 5 + p) * NCH + c];
                dsum += bt.b[p] * Aq[p] * C;
            }
            sden[sl] = dsum;
        }
        __syncthreads();
    }

    // ---- Phase 3b: rescan + output ----
    float kv[5];
#pragma unroll
    for (int p = 0; p < 5; p++)
        kv[p] = g_ckv[(((size_t)bh * 5 + p) * NCH + c) * DH + d];

    const size_t obase = ((size_t)(b * S_LEN + c * CHS)) * DMODEL + h * DH + d;

#pragma unroll 4
    for (int s = 0; s < CHS; s++) {
        float qv   = sq[s][d];
        float kval = sk[s][d];
        float vval = sv[s][d];

        float tk[5];
        cheb5(clampx(kval * 0.125f), tk);
#pragma unroll
        for (int p = 0; p < 5; p++) kv[p] += tk[p] * vval;

        float tq[5];
        cheb5(clampx(qv * 0.125f), tq);
        float num = 0.0f;
#pragma unroll
        for (int p = 0; p < 5; p++) num += bt.b[p] * tq[p] * kv[p];

        float res = num / (sden[s] + 1e-7f);
        __nv_bfloat16 hi = __float2bfloat16(res);
        size_t idx = obase + (size_t)s * DMODEL;
        g_ath[idx] = hi;
        g_atl[idx] = __float2bfloat16(res - __bfloat162float(hi));
    }
}

// ---------------------------------------------------------------------------
extern "C" void kernel_launch(void* const* d_in, const int* in_sizes, int n_in,
                              void* d_out, int out_size)
{
    const float* x     = (const float*)d_in[0];   // (2,1024,1024)
    const float* W_in  = (const float*)d_in[1];   // (3072,1024)
    const float* W_out = (const float*)d_in[2];   // (1024,1024)
    float* out = (float*)d_out;                   // (2,1024,1024)

    float* qkv;
    cudaGetSymbolAddress((void**)&qkv, g_qkv);
    __nv_bfloat16 *xh, *xl, *wih, *wil, *woh, *wol, *ath, *atl;
    cudaGetSymbolAddress((void**)&xh,  g_xh);
    cudaGetSymbolAddress((void**)&xl,  g_xl);
    cudaGetSymbolAddress((void**)&wih, g_wih);
    cudaGetSymbolAddress((void**)&wil, g_wil);
    cudaGetSymbolAddress((void**)&woh, g_woh);
    cudaGetSymbolAddress((void**)&wol, g_wol);
    cudaGetSymbolAddress((void**)&ath, g_ath);
    cudaGetSymbolAddress((void**)&atl, g_atl);

    // beta[p] = tail[p+1] / sum(tail[1..5])
    double alpha[6], tail[7];
    tail[6] = 0.0;
    for (int j = 5; j >= 0; j--) {
        alpha[j] = pow((double)(j + 1), -1.5);
        tail[j] = tail[j + 1] + alpha[j];
    }
    double bsum = tail[1] + tail[2] + tail[3] + tail[4] + tail[5];
    Betas bt;
    for (int p = 0; p < 5; p++) bt.b[p] = (float)(tail[p + 1] / bsum);

    const int M = BATCH * S_LEN;           // 2048
    const int nx = M * DMODEL;             // 2M
    const int nw1 = 3 * DMODEL * DMODEL;   // 3M
    const int nw2 = DMODEL * DMODEL;       // 1M

    cudaFuncSetAttribute(gemm_split<128>, cudaFuncAttributeMaxDynamicSharedMemorySize, 98304);
    cudaFuncSetAttribute(gemm_split<64>,  cudaFuncAttributeMaxDynamicSharedMemorySize, 73728);

    split3<<<(nx + nw1 + nw2) / 4 / 256, 256>>>(x, xh, xl, nx,
                                                W_in, wih, wil, nw1,
                                                W_out, woh, wol, nw2);
    gemm_split<128><<<dim3(3 * DMODEL / 128, M / 128), 256, 98304>>>(
        xh, xl, wih, wil, qkv, M, 3 * DMODEL, DMODEL);
    scan_fused<<<NBLK, 64>>>(bt);
    gemm_split<64><<<dim3(DMODEL / 64, M / 128), 256, 73728>>>(
        ath, atl, woh, wol, out, M, DMODEL, DMODEL);
}